// round 1
// baseline (speedup 1.0000x reference)
#include <cuda_runtime.h>
#include <cuda_bf16.h>

// Problem constants (fixed shapes from reference)
#define NN 25000
#define PP 400000
#define FF 224      // = TF = TH*FH
#define KK 32
#define HH 4
#define THH 7
#define DV 56
#define NORD 15

#define EPB 32     // edges per block
#define TPB 224    // threads per block (edge kernel)
#define CT 32      // c-tile rows staged in smem

// -------- scratch (static device arrays; no allocation allowed) --------
__device__ float g_q[NN * FF];
__device__ float g_k[NN * FF];
__device__ float g_v[NN * FF];

__device__ __forceinline__ float silu_f(float x) {
    return x / (1.0f + __expf(-x));
}

// -------- zero output --------
__global__ void zero_kernel(float* out, int n) {
    int i = blockIdx.x * blockDim.x + threadIdx.x;
    for (; i < n; i += gridDim.x * blockDim.x) out[i] = 0.0f;
}

// -------- per-node q,k,v precompute --------
// q[n,t,i] = silu(sum_j Wq[t,i,j] * x[n, t*32+j])   (t in 0..6, i in 0..31)
// k same with Wk;  v[n,h,i] = sum_j Wv[h,i,j] * x[n, h*56+j]  (no silu)
__global__ __launch_bounds__(224) void node_kernel(
    const float* __restrict__ x,
    const float* __restrict__ Wq,
    const float* __restrict__ Wk,
    const float* __restrict__ Wv)
{
    __shared__ float xs[FF];
    int n = blockIdx.x;
    int f = threadIdx.x;
    xs[f] = x[n * FF + f];
    __syncthreads();

    // q / k
    {
        int t = f >> 5;
        int i = f & 31;
        const float* wq = Wq + (t * 32 + i) * 32;
        const float* wk = Wk + (t * 32 + i) * 32;
        const float* xb = xs + t * 32;
        float aq = 0.f, ak = 0.f;
#pragma unroll
        for (int j = 0; j < 32; j++) {
            float xv = xb[j];
            aq = fmaf(__ldg(&wq[j]), xv, aq);
            ak = fmaf(__ldg(&wk[j]), xv, ak);
        }
        g_q[n * FF + f] = silu_f(aq);
        g_k[n * FF + f] = silu_f(ak);
    }
    // v
    {
        int h = f / DV;
        int i = f % DV;
        const float* wv = Wv + (h * DV + i) * DV;
        const float* xb = xs + h * DV;
        float av = 0.f;
#pragma unroll 8
        for (int j = 0; j < DV; j++) av = fmaf(__ldg(&wv[j]), xb[j], av);
        g_v[n * FF + f] = av;
    }
}

// -------- edge kernel --------
// dyn smem: w2s [CT][224] then Hs [224][32]
extern "C" __global__ void __launch_bounds__(TPB) edge_kernel(
    const float* __restrict__ rbf,
    const float* __restrict__ ylm,
    const float* __restrict__ cut,
    const int*   __restrict__ idx_i,
    const int*   __restrict__ idx_j,
    const float* __restrict__ ev,
    const float* __restrict__ W1r, const float* __restrict__ b1r,
    const float* __restrict__ W2r, const float* __restrict__ b2r,
    const float* __restrict__ W1s, const float* __restrict__ b1s,
    const float* __restrict__ W2s, const float* __restrict__ b2s,
    float* __restrict__ out_x, float* __restrict__ out_ev)
{
    extern __shared__ float dyn[];
    float* w2s = dyn;                 // CT * 224
    float* Hs  = dyn + CT * FF;       // 224 * 32  (c-major, edge-minor)

    __shared__ float rbfc[EPB][KK];
    __shared__ float con_s[EPB][3];
    __shared__ float alpha_s[EPB][THH];
    __shared__ float ylm_s[EPB][NORD];
    __shared__ int   ii_s[EPB], jj_s[EPB];
    __shared__ float cut_s[EPB];

    const int tid = threadIdx.x;
    const int p0  = blockIdx.x * EPB;

    if (tid < EPB) {
        int p = p0 + tid;
        ii_s[tid]  = idx_i[p];
        jj_s[tid]  = idx_j[p];
        cut_s[tid] = cut[p];
    }
    if (tid < EPB * THH) ((float*)alpha_s)[tid] = 0.0f;
    __syncthreads();

    // rbf * cut into smem
    for (int idx = tid; idx < EPB * KK; idx += TPB) {
        int e = idx >> 5, kk = idx & 31;
        rbfc[e][kk] = rbf[(p0 + e) * KK + kk] * cut_s[e];
    }
    // ylm into smem
    for (int idx = tid; idx < EPB * NORD; idx += TPB) {
        int e = idx / NORD, o = idx % NORD;
        ylm_s[e][o] = ylm[(p0 + e) * NORD + o];
    }
    // l0 contraction per edge
    if (tid < EPB) {
        int e = tid;
        const float* evi = ev + (size_t)ii_s[e] * NORD;
        const float* evj = ev + (size_t)jj_s[e] * NORD;
        float c0 = 0.f, c1 = 0.f, c2 = 0.f;
#pragma unroll
        for (int o = 0; o < 3; o++)  { float d = __ldg(&evj[o]) - __ldg(&evi[o]); c0 = fmaf(d, d, c0); }
#pragma unroll
        for (int o = 3; o < 8; o++)  { float d = __ldg(&evj[o]) - __ldg(&evi[o]); c1 = fmaf(d, d, c1); }
#pragma unroll
        for (int o = 8; o < 15; o++) { float d = __ldg(&evj[o]) - __ldg(&evi[o]); c2 = fmaf(d, d, c2); }
        con_s[e][0] = c0; con_s[e][1] = c1; con_s[e][2] = c2;
    }
    __syncthreads();

    // H compute: Hs[c][e] = silu(rbfc@W1r + b1r)  (c<112)
    //            Hs[112+c][e] = silu(con@W1s + b1s)
    for (int idx = tid; idx < EPB * 112; idx += TPB) {
        int e = idx / 112, c = idx % 112;
        float a1 = __ldg(&b1r[c]);
#pragma unroll 8
        for (int kk = 0; kk < 32; kk++)
            a1 = fmaf(rbfc[e][kk], __ldg(&W1r[kk * 112 + c]), a1);
        float a2 = __ldg(&b1s[c]);
        a2 = fmaf(con_s[e][0], __ldg(&W1s[0 * 112 + c]), a2);
        a2 = fmaf(con_s[e][1], __ldg(&W1s[1 * 112 + c]), a2);
        a2 = fmaf(con_s[e][2], __ldg(&W1s[2 * 112 + c]), a2);
        Hs[c * EPB + e]         = silu_f(a1);
        Hs[(112 + c) * EPB + e] = silu_f(a2);
    }

    // thread tiling: 8 edge-groups (4 edges each) x 28 column-chunks
    // chunk covers cols [f0, f0+4) and [f0+112, f0+116)
    const int eg    = tid / 28;       // 0..7
    const int chunk = tid % 28;       // 0..27
    const int e0 = eg * 4;
    const int f0 = chunk * 4;         // 0..108
    const int hA = f0 >> 5;           // head of first half (0..3)
    const int hB = (f0 + 112) >> 5;   // head of second half (3..6)

    float G[4][8];
    float accA[4], accB[4];
    {
        float b2c[8];
#pragma unroll
        for (int u = 0; u < 4; u++) {
            b2c[u]     = __ldg(&b2r[f0 + u])       + __ldg(&b2s[f0 + u]);
            b2c[4 + u] = __ldg(&b2r[f0 + 112 + u]) + __ldg(&b2s[f0 + 112 + u]);
        }
#pragma unroll
        for (int e = 0; e < 4; e++) {
            const size_t ri = (size_t)ii_s[e0 + e] * FF;
            const size_t rj = (size_t)jj_s[e0 + e] * FF;
            float4 qa = *(const float4*)&g_q[ri + f0];
            float4 qb = *(const float4*)&g_q[ri + f0 + 112];
            float4 ka = *(const float4*)&g_k[rj + f0];
            float4 kb = *(const float4*)&g_k[rj + f0 + 112];
            G[e][0] = qa.x * ka.x; G[e][1] = qa.y * ka.y;
            G[e][2] = qa.z * ka.z; G[e][3] = qa.w * ka.w;
            G[e][4] = qb.x * kb.x; G[e][5] = qb.y * kb.y;
            G[e][6] = qb.z * kb.z; G[e][7] = qb.w * kb.w;
            float a = 0.f, b = 0.f;
#pragma unroll
            for (int u = 0; u < 4; u++) {
                a = fmaf(b2c[u],     G[e][u],     a);
                b = fmaf(b2c[4 + u], G[e][4 + u], b);
            }
            accA[e] = a; accB[e] = b;
        }
    }

    // main trilinear loop over c in tiles of CT
#pragma unroll 1
    for (int ct = 0; ct < FF / CT; ct++) {
        __syncthreads();   // protects w2s reuse + (first iter) Hs completion
        // stage W2cat rows [ct*CT, ct*CT+CT)
        for (int idx = tid; idx < CT * FF; idx += TPB) {
            int cl = idx / FF, f = idx % FF;
            int cg = ct * CT + cl;
            w2s[cl * FF + f] = (cg < 112) ? __ldg(&W2r[cg * FF + f])
                                          : __ldg(&W2s[(cg - 112) * FF + f]);
        }
        __syncthreads();
        const float* hptr = Hs + (ct * CT) * EPB + e0;
        const float* wptr = w2s + f0;
#pragma unroll 8
        for (int cl = 0; cl < CT; cl++) {
            float4 w0 = *(const float4*)(wptr);
            float4 w1 = *(const float4*)(wptr + 112);
            float4 h4 = *(const float4*)(hptr);
            wptr += FF; hptr += EPB;
            float hv[4] = {h4.x, h4.y, h4.z, h4.w};
#pragma unroll
            for (int e = 0; e < 4; e++) {
                float sA = w0.x * G[e][0];
                sA = fmaf(w0.y, G[e][1], sA);
                sA = fmaf(w0.z, G[e][2], sA);
                sA = fmaf(w0.w, G[e][3], sA);
                float sB = w1.x * G[e][4];
                sB = fmaf(w1.y, G[e][5], sB);
                sB = fmaf(w1.z, G[e][6], sB);
                sB = fmaf(w1.w, G[e][7], sB);
                accA[e] = fmaf(hv[e], sA, accA[e]);
                accB[e] = fmaf(hv[e], sB, accB[e]);
            }
        }
    }

#pragma unroll
    for (int e = 0; e < 4; e++) {
        atomicAdd(&alpha_s[e0 + e][hA], accA[e]);
        atomicAdd(&alpha_s[e0 + e][hB], accB[e]);
    }
    __syncthreads();

    // ---- scatter x_att: thread f owns output column f; run-length aggregate over sorted i
    {
        int f = tid;                 // 0..223
        int hh = f / DV;             // 0..3
        float run = 0.f;
        int iprev = ii_s[0];
#pragma unroll 4
        for (int e = 0; e < EPB; e++) {
            int i = ii_s[e];
            if (i != iprev) {
                atomicAdd(&out_x[(size_t)iprev * FF + f], run);
                run = 0.f; iprev = i;
            }
            float a = alpha_s[e][hh] * cut_s[e];
            run = fmaf(a, __ldg(&g_v[(size_t)jj_s[e] * FF + f]), run);
        }
        atomicAdd(&out_x[(size_t)iprev * FF + f], run);
    }
    // ---- scatter ev_att
    if (tid < NORD) {
        int o  = tid;
        int hh = (o < 3) ? 4 : ((o < 8) ? 5 : 6);
        float run = 0.f;
        int iprev = ii_s[0];
        for (int e = 0; e < EPB; e++) {
            int i = ii_s[e];
            if (i != iprev) {
                atomicAdd(&out_ev[(size_t)iprev * NORD + o], run);
                run = 0.f; iprev = i;
            }
            run = fmaf(alpha_s[e][hh] * cut_s[e], ylm_s[e][o], run);
        }
        atomicAdd(&out_ev[(size_t)iprev * NORD + o], run);
    }
}

extern "C" void kernel_launch(void* const* d_in, const int* in_sizes, int n_in,
                              void* d_out, int out_size) {
    const float* x     = (const float*)d_in[0];
    const float* ev    = (const float*)d_in[1];
    const float* rbf   = (const float*)d_in[2];
    const float* ylm   = (const float*)d_in[3];
    const float* cut   = (const float*)d_in[4];
    const int*   idx_i = (const int*)d_in[5];
    const int*   idx_j = (const int*)d_in[6];
    const float* W1r   = (const float*)d_in[7];
    const float* b1r   = (const float*)d_in[8];
    const float* W2r   = (const float*)d_in[9];
    const float* b2r   = (const float*)d_in[10];
    const float* W1s   = (const float*)d_in[11];
    const float* b1s   = (const float*)d_in[12];
    const float* W2s   = (const float*)d_in[13];
    const float* b2s   = (const float*)d_in[14];
    const float* Wq    = (const float*)d_in[15];
    const float* Wk    = (const float*)d_in[16];
    const float* Wv    = (const float*)d_in[17];

    float* out   = (float*)d_out;
    float* out_x = out;                       // [N,224]
    float* out_ev = out + (size_t)NN * FF;    // [N,15]

    static bool attr_done = false;
    // setting an attribute is idempotent and not a stream op; safe under capture
    cudaFuncSetAttribute(edge_kernel, cudaFuncAttributeMaxDynamicSharedMemorySize,
                         (CT * FF + FF * EPB) * (int)sizeof(float));
    (void)attr_done;

    // 1) zero outputs (atomics accumulate)
    zero_kernel<<<256, 256>>>(out, out_size);

    // 2) per-node q,k,v
    node_kernel<<<NN, 224>>>(x, Wq, Wk, Wv);

    // 3) edges
    size_t dynsmem = (size_t)(CT * FF + FF * EPB) * sizeof(float);
    edge_kernel<<<PP / EPB, TPB, dynsmem>>>(
        rbf, ylm, cut, idx_i, idx_j, ev,
        W1r, b1r, W2r, b2r, W1s, b1s, W2s, b2s,
        out_x, out_ev);
}

// round 7
// speedup vs baseline: 1.2769x; 1.2769x over previous
#include <cuda_runtime.h>
#include <cuda_bf16.h>

// Problem constants (fixed shapes from reference)
#define NN 25000
#define PP 400000
#define FF 224      // = TF = TH*FH
#define KK 32
#define HH 4
#define THH 7
#define DV 56
#define NORD 15

#define EPB 32     // edges per block
#define TPB 224    // threads per block (edge kernel)
#define CT 32      // c-tile rows staged in smem
#define HP 36      // Hs row pitch (padded: 4-way max conflict, float4 aligned)

// -------- scratch (static device arrays; no allocation allowed) --------
__device__ float g_q[NN * FF];
__device__ float g_k[NN * FF];
__device__ float g_v[NN * FF];

__device__ __forceinline__ float silu_f(float x) {
    return x / (1.0f + __expf(-x));
}

// -------- per-node q,k,v precompute + output zeroing --------
__global__ __launch_bounds__(224) void node_kernel(
    const float* __restrict__ x,
    const float* __restrict__ Wq,
    const float* __restrict__ Wk,
    const float* __restrict__ Wv,
    float* __restrict__ out_x,
    float* __restrict__ out_ev)
{
    __shared__ float xs[FF];
    int n = blockIdx.x;
    int f = threadIdx.x;
    xs[f] = x[n * FF + f];
    // zero outputs (atomics accumulate into them later)
    out_x[(size_t)n * FF + f] = 0.0f;
    if (f < NORD) out_ev[(size_t)n * NORD + f] = 0.0f;
    __syncthreads();

    // q / k
    {
        int t = f >> 5;
        int i = f & 31;
        const float* wq = Wq + (t * 32 + i) * 32;
        const float* wk = Wk + (t * 32 + i) * 32;
        const float* xb = xs + t * 32;
        float aq = 0.f, ak = 0.f;
#pragma unroll
        for (int j = 0; j < 32; j++) {
            float xv = xb[j];
            aq = fmaf(__ldg(&wq[j]), xv, aq);
            ak = fmaf(__ldg(&wk[j]), xv, ak);
        }
        g_q[n * FF + f] = silu_f(aq);
        g_k[n * FF + f] = silu_f(ak);
    }
    // v
    {
        int h = f / DV;
        int i = f % DV;
        const float* wv = Wv + (h * DV + i) * DV;
        const float* xb = xs + h * DV;
        float av = 0.f;
#pragma unroll 8
        for (int j = 0; j < DV; j++) av = fmaf(__ldg(&wv[j]), xb[j], av);
        g_v[n * FF + f] = av;
    }
}

// -------- edge kernel --------
// dyn smem: w2s [CT][224] then Hs [224][HP]
extern "C" __global__ void __launch_bounds__(TPB, 3) edge_kernel(
    const float* __restrict__ rbf,
    const float* __restrict__ ylm,
    const float* __restrict__ cut,
    const int*   __restrict__ idx_i,
    const int*   __restrict__ idx_j,
    const float* __restrict__ ev,
    const float* __restrict__ W1r, const float* __restrict__ b1r,
    const float* __restrict__ W2r, const float* __restrict__ b2r,
    const float* __restrict__ W1s, const float* __restrict__ b1s,
    const float* __restrict__ W2s, const float* __restrict__ b2s,
    float* __restrict__ out_x, float* __restrict__ out_ev)
{
    extern __shared__ float dyn[];
    float* w2s = dyn;                 // CT * FF
    float* Hs  = dyn + CT * FF;       // 224 * HP  (c-major, padded)

    __shared__ float rbfc[EPB][KK];
    __shared__ float con_s[EPB][3];
    __shared__ float alpha_s[EPB][THH];
    __shared__ float ylm_s[EPB][NORD];
    __shared__ int   ii_s[EPB], jj_s[EPB];
    __shared__ float cut_s[EPB];

    const int tid = threadIdx.x;
    const int p0  = blockIdx.x * EPB;

    if (tid < EPB) {
        int p = p0 + tid;
        ii_s[tid]  = idx_i[p];
        jj_s[tid]  = idx_j[p];
        cut_s[tid] = cut[p];
    }
    if (tid < EPB * THH) ((float*)alpha_s)[tid] = 0.0f;
    __syncthreads();

    // rbf * cut into smem
    for (int idx = tid; idx < EPB * KK; idx += TPB) {
        int e = idx >> 5, kk = idx & 31;
        rbfc[e][kk] = rbf[(p0 + e) * KK + kk] * cut_s[e];
    }
    // ylm into smem
    for (int idx = tid; idx < EPB * NORD; idx += TPB) {
        int e = idx / NORD, o = idx % NORD;
        ylm_s[e][o] = ylm[(p0 + e) * NORD + o];
    }
    // l0 contraction per edge
    if (tid < EPB) {
        int e = tid;
        const float* evi = ev + (size_t)ii_s[e] * NORD;
        const float* evj = ev + (size_t)jj_s[e] * NORD;
        float c0 = 0.f, c1 = 0.f, c2 = 0.f;
#pragma unroll
        for (int o = 0; o < 3; o++)  { float d = __ldg(&evj[o]) - __ldg(&evi[o]); c0 = fmaf(d, d, c0); }
#pragma unroll
        for (int o = 3; o < 8; o++)  { float d = __ldg(&evj[o]) - __ldg(&evi[o]); c1 = fmaf(d, d, c1); }
#pragma unroll
        for (int o = 8; o < 15; o++) { float d = __ldg(&evj[o]) - __ldg(&evi[o]); c2 = fmaf(d, d, c2); }
        con_s[e][0] = c0; con_s[e][1] = c1; con_s[e][2] = c2;
    }
    __syncthreads();

    // ---- H compute ----
    // Thread owns fixed c = tid % 112; visits 16 edges (e = 2k + (tid>=112)).
    // W1r column hoisted into registers (32 coalesced LDGs, c consecutive in warp).
    {
        const int cH = tid % 112;
        const int eBase = (tid >= 112) ? 1 : 0;
        float w1rr[32];
#pragma unroll
        for (int kk = 0; kk < 32; kk++) w1rr[kk] = __ldg(&W1r[kk * 112 + cH]);
        const float w1s0 = __ldg(&W1s[cH]);
        const float w1s1 = __ldg(&W1s[112 + cH]);
        const float w1s2 = __ldg(&W1s[224 + cH]);
        const float b1rc = __ldg(&b1r[cH]);
        const float b1sc = __ldg(&b1s[cH]);
#pragma unroll 4
        for (int k2 = 0; k2 < 16; k2++) {
            const int e = 2 * k2 + eBase;
            const float4* r4 = (const float4*)&rbfc[e][0];
            float a1 = b1rc;
#pragma unroll
            for (int q = 0; q < 8; q++) {
                float4 rv = r4[q];
                a1 = fmaf(rv.x, w1rr[4 * q + 0], a1);
                a1 = fmaf(rv.y, w1rr[4 * q + 1], a1);
                a1 = fmaf(rv.z, w1rr[4 * q + 2], a1);
                a1 = fmaf(rv.w, w1rr[4 * q + 3], a1);
            }
            float a2 = b1sc;
            a2 = fmaf(con_s[e][0], w1s0, a2);
            a2 = fmaf(con_s[e][1], w1s1, a2);
            a2 = fmaf(con_s[e][2], w1s2, a2);
            Hs[cH * HP + e]         = silu_f(a1);
            Hs[(cH + 112) * HP + e] = silu_f(a2);
        }
    }

    // ---- main trilinear: accumulate wsum[e, f] = sum_c H[e,c] * W2cat[c,f] ----
    // thread tiling: 8 edge-groups (4 edges) x 28 column-chunks (4 cols + 4 cols@+112)
    const int eg    = tid / 28;       // 0..7
    const int chunk = tid % 28;       // 0..27
    const int e0 = eg * 4;
    const int f0 = chunk * 4;         // 0..108
    const int hA = f0 >> 5;           // 0..3
    const int hB = (f0 + 112) >> 5;   // 3..6

    float acc[4][8];
    {
        // init with combined bias (per-f, same for each edge)
        float b2c[8];
#pragma unroll
        for (int u = 0; u < 4; u++) {
            b2c[u]     = __ldg(&b2r[f0 + u])       + __ldg(&b2s[f0 + u]);
            b2c[4 + u] = __ldg(&b2r[f0 + 112 + u]) + __ldg(&b2s[f0 + 112 + u]);
        }
#pragma unroll
        for (int e = 0; e < 4; e++)
#pragma unroll
            for (int u = 0; u < 8; u++) acc[e][u] = b2c[u];
    }

#pragma unroll 1
    for (int ct = 0; ct < FF / CT; ct++) {
        __syncthreads();   // w2s reuse + (first iter) Hs completion
        // stage W2cat rows [ct*CT, ct*CT+CT) — float4 vectorized
        // (rows are 896B, 16B-aligned in gmem and smem)
        for (int idx = tid; idx < CT * (FF / 4); idx += TPB) {
            int cl = idx / (FF / 4);       // 0..31
            int f4 = idx % (FF / 4);       // 0..55
            int cg = ct * CT + cl;
            const float4* src = (cg < 112)
                ? (const float4*)(W2r + (size_t)cg * FF)
                : (const float4*)(W2s + (size_t)(cg - 112) * FF);
            ((float4*)(w2s + cl * FF))[f4] = __ldg(&src[f4]);
        }
        __syncthreads();
        const float* hbase = Hs + (ct * CT) * HP + e0;
        const float* wbase = w2s + f0;
#pragma unroll 8
        for (int cl = 0; cl < CT; cl++) {
            float4 w0 = *(const float4*)(wbase + cl * FF);
            float4 w1 = *(const float4*)(wbase + cl * FF + 112);
            float4 h4 = *(const float4*)(hbase + cl * HP);
            float hv[4] = {h4.x, h4.y, h4.z, h4.w};
#pragma unroll
            for (int e = 0; e < 4; e++) {
                acc[e][0] = fmaf(hv[e], w0.x, acc[e][0]);
                acc[e][1] = fmaf(hv[e], w0.y, acc[e][1]);
                acc[e][2] = fmaf(hv[e], w0.z, acc[e][2]);
                acc[e][3] = fmaf(hv[e], w0.w, acc[e][3]);
                acc[e][4] = fmaf(hv[e], w1.x, acc[e][4]);
                acc[e][5] = fmaf(hv[e], w1.y, acc[e][5]);
                acc[e][6] = fmaf(hv[e], w1.z, acc[e][6]);
                acc[e][7] = fmaf(hv[e], w1.w, acc[e][7]);
            }
        }
    }

    // ---- apply G = q_i * k_j elementwise, reduce over the 8 owned columns ----
#pragma unroll
    for (int e = 0; e < 4; e++) {
        const size_t ri = (size_t)ii_s[e0 + e] * FF;
        const size_t rj = (size_t)jj_s[e0 + e] * FF;
        float4 qa = *(const float4*)&g_q[ri + f0];
        float4 qb = *(const float4*)&g_q[ri + f0 + 112];
        float4 ka = *(const float4*)&g_k[rj + f0];
        float4 kb = *(const float4*)&g_k[rj + f0 + 112];
        float aA = acc[e][0] * (qa.x * ka.x);
        aA = fmaf(acc[e][1], qa.y * ka.y, aA);
        aA = fmaf(acc[e][2], qa.z * ka.z, aA);
        aA = fmaf(acc[e][3], qa.w * ka.w, aA);
        float aB = acc[e][4] * (qb.x * kb.x);
        aB = fmaf(acc[e][5], qb.y * kb.y, aB);
        aB = fmaf(acc[e][6], qb.z * kb.z, aB);
        aB = fmaf(acc[e][7], qb.w * kb.w, aB);
        atomicAdd(&alpha_s[e0 + e][hA], aA);
        atomicAdd(&alpha_s[e0 + e][hB], aB);
    }
    __syncthreads();

    // ---- scatter x_att: thread f owns output column f; run-length aggregate over sorted i
    {
        int f = tid;                 // 0..223
        int hh = f / DV;             // 0..3
        float run = 0.f;
        int iprev = ii_s[0];
#pragma unroll 4
        for (int e = 0; e < EPB; e++) {
            int i = ii_s[e];
            if (i != iprev) {
                atomicAdd(&out_x[(size_t)iprev * FF + f], run);
                run = 0.f; iprev = i;
            }
            float a = alpha_s[e][hh] * cut_s[e];
            run = fmaf(a, __ldg(&g_v[(size_t)jj_s[e] * FF + f]), run);
        }
        atomicAdd(&out_x[(size_t)iprev * FF + f], run);
    }
    // ---- scatter ev_att
    if (tid < NORD) {
        int o  = tid;
        int hh = (o < 3) ? 4 : ((o < 8) ? 5 : 6);
        float run = 0.f;
        int iprev = ii_s[0];
        for (int e = 0; e < EPB; e++) {
            int i = ii_s[e];
            if (i != iprev) {
                atomicAdd(&out_ev[(size_t)iprev * NORD + o], run);
                run = 0.f; iprev = i;
            }
            run = fmaf(alpha_s[e][hh] * cut_s[e], ylm_s[e][o], run);
        }
        atomicAdd(&out_ev[(size_t)iprev * NORD + o], run);
    }
}

extern "C" void kernel_launch(void* const* d_in, const int* in_sizes, int n_in,
                              void* d_out, int out_size) {
    const float* x     = (const float*)d_in[0];
    const float* ev    = (const float*)d_in[1];
    const float* rbf   = (const float*)d_in[2];
    const float* ylm   = (const float*)d_in[3];
    const float* cut   = (const float*)d_in[4];
    const int*   idx_i = (const int*)d_in[5];
    const int*   idx_j = (const int*)d_in[6];
    const float* W1r   = (const float*)d_in[7];
    const float* b1r   = (const float*)d_in[8];
    const float* W2r   = (const float*)d_in[9];
    const float* b2r   = (const float*)d_in[10];
    const float* W1s   = (const float*)d_in[11];
    const float* b1s   = (const float*)d_in[12];
    const float* W2s   = (const float*)d_in[13];
    const float* b2s   = (const float*)d_in[14];
    const float* Wq    = (const float*)d_in[15];
    const float* Wk    = (const float*)d_in[16];
    const float* Wv    = (const float*)d_in[17];

    float* out    = (float*)d_out;
    float* out_x  = out;                       // [N,224]
    float* out_ev = out + (size_t)NN * FF;     // [N,15]

    const int dynsmem = (CT * FF + FF * HP) * (int)sizeof(float);
    cudaFuncSetAttribute(edge_kernel, cudaFuncAttributeMaxDynamicSharedMemorySize, dynsmem);

    // 1) per-node q,k,v + zero outputs
    node_kernel<<<NN, 224>>>(x, Wq, Wk, Wv, out_x, out_ev);

    // 2) edges
    edge_kernel<<<PP / EPB, TPB, dynsmem>>>(
        rbf, ylm, cut, idx_i, idx_j, ev,
        W1r, b1r, W2r, b2r, W1s, b1s, W2s, b2s,
        out_x, out_ev);
}